// round 13
// baseline (speedup 1.0000x reference)
#include <cuda_runtime.h>
#include <cuda_fp16.h>
#include <cstdint>

#define NN      50000
#define NF      512
#define NHID1   256     // 8 heads * 32
#define NHID2   512     // 8 heads * 64
#define NCLS    64
#define NHEADS  8
#define C1      32
#define C2      64
#define E0      800000
#define NEG_SLOPE 0.2f

// ---------------- scratch (device globals; no allocs allowed) ----------------
__device__ __half g_h1[(size_t)NN * NHID1];
__device__ float  g_agg1[(size_t)NN * NHID1];
__device__ __half g_h2[(size_t)NN * NHID2];
__device__ float  g_es[(size_t)NN * NHEADS];
__device__ float  g_ed[(size_t)NN * NHEADS];
__device__ int    g_deg[NN];
__device__ int    g_off[NN + 1];
__device__ int    g_cur[NN];
__device__ int    g_csr[E0];                   // src indices sorted by dst

// ---------------- CSR build ----------------
__global__ void histogram_kernel(const int* __restrict__ ei, int* __restrict__ deg) {
    int e = blockIdx.x * blockDim.x + threadIdx.x;
    if (e >= E0) return;
    atomicAdd(deg + ei[E0 + e], 1);
}

__global__ void scan_kernel(const int* __restrict__ deg, int* __restrict__ off,
                            int* __restrict__ cur) {
    __shared__ int sh[1024];
    int t = threadIdx.x;
    const int CHUNK = (NN + 1023) / 1024;  // 49
    int beg = t * CHUNK;
    int end = min(beg + CHUNK, NN);
    int s = 0;
    for (int i = beg; i < end; i++) s += deg[i];
    sh[t] = s;
    __syncthreads();
    for (int st = 1; st < 1024; st <<= 1) {
        int a = (t >= st) ? sh[t - st] : 0;
        __syncthreads();
        sh[t] += a;
        __syncthreads();
    }
    int run = (t == 0) ? 0 : sh[t - 1];
    for (int i = beg; i < end; i++) {
        off[i] = run;
        cur[i] = run;
        run += deg[i];
    }
    if (t == 1023) off[NN] = E0;
}

__global__ void fill_kernel(const int* __restrict__ ei, int* __restrict__ cur,
                            int* __restrict__ csr) {
    int e = blockIdx.x * blockDim.x + threadIdx.x;
    if (e >= E0) return;
    int src = ei[e];
    int dst = ei[E0 + e];
    int pos = atomicAdd(cur + dst, 1);
    csr[pos] = src;
}

// ---------------- fp16 tensor-core GEMM (m16n8k16), cp.async 2-stage pipeline ----------------
__device__ __forceinline__ uint32_t pack_h2(float lo, float hi) {
    __half2 h = __floats2half2_rn(lo, hi);
    return *(uint32_t*)&h;
}

__device__ __forceinline__ void mma_f16(float4& d, const uint32_t* a, const uint32_t* b) {
    asm volatile("mma.sync.aligned.m16n8k16.row.col.f32.f16.f16.f32 "
                 "{%0,%1,%2,%3}, {%4,%5,%6,%7}, {%8,%9}, {%0,%1,%2,%3};"
                 : "+f"(d.x), "+f"(d.y), "+f"(d.z), "+f"(d.w)
                 : "r"(a[0]), "r"(a[1]), "r"(a[2]), "r"(a[3]), "r"(b[0]), "r"(b[1]));
}

__device__ __forceinline__ void cp16(float* smem, const float* gmem, bool pred) {
    uint32_t s = (uint32_t)__cvta_generic_to_shared(smem);
    int sz = pred ? 16 : 0;
    asm volatile("cp.async.cg.shared.global [%0], [%1], 16, %2;"
                 :: "r"(s), "l"(gmem), "r"(sz));
}

// C[M,N](fp16) = A[M,K]*B[K,N]; 128x128x32 tiles, 8 warps, warp tile 64x32.
#define AS_STRIDE 40
#define BS_STRIDE 132
#define A_ELE (128 * AS_STRIDE)
#define B_ELE (32 * BS_STRIDE)
#define GEMM_SMEM (2 * (A_ELE + B_ELE) * 4)
__global__ void __launch_bounds__(256, 2)
f16gemm(const float* __restrict__ A, const float* __restrict__ B,
        __half* __restrict__ C, int M, int K, int N) {
    extern __shared__ float sm[];
    float* As = sm;                 // 2 stages
    float* Bs = sm + 2 * A_ELE;
    int tid = threadIdx.x;
    int lane = tid & 31;
    int warp = tid >> 5;
    int wm = warp & 1;
    int wn = warp >> 1;
    int bm = blockIdx.y * 128, bn = blockIdx.x * 128;

    int gid = lane >> 2;
    int tig = lane & 3;

    int arow = tid >> 3;            // 0..31, +p*32
    int acol = (tid & 7) * 4;
    int bkr = tid >> 5;             // 0..7, +p*8
    int bnc = (tid & 31) * 4;

    float4 acc[4][4];
#pragma unroll
    for (int i = 0; i < 4; i++)
#pragma unroll
        for (int j = 0; j < 4; j++) acc[i][j] = make_float4(0.f, 0.f, 0.f, 0.f);

    int nIter = K >> 5;

    {
#pragma unroll
        for (int p = 0; p < 4; p++) {
            int row = arow + p * 32;
            cp16(&As[row * AS_STRIDE + acol], A + (size_t)(bm + row) * K + acol, bm + row < M);
        }
#pragma unroll
        for (int p = 0; p < 4; p++) {
            int k = bkr + p * 8;
            cp16(&Bs[k * BS_STRIDE + bnc], B + (size_t)k * N + bn + bnc, true);
        }
        asm volatile("cp.async.commit_group;");
    }

    for (int it = 0; it < nIter; it++) {
        if (it + 1 < nIter) {
            int k0 = (it + 1) << 5;
            float* as = As + ((it + 1) & 1) * A_ELE;
            float* bs = Bs + ((it + 1) & 1) * B_ELE;
#pragma unroll
            for (int p = 0; p < 4; p++) {
                int row = arow + p * 32;
                cp16(&as[row * AS_STRIDE + acol], A + (size_t)(bm + row) * K + k0 + acol, bm + row < M);
            }
#pragma unroll
            for (int p = 0; p < 4; p++) {
                int k = bkr + p * 8;
                cp16(&bs[k * BS_STRIDE + bnc], B + (size_t)(k0 + k) * N + bn + bnc, true);
            }
            asm volatile("cp.async.commit_group;");
            asm volatile("cp.async.wait_group 1;");
        } else {
            asm volatile("cp.async.wait_group 0;");
        }
        __syncthreads();

        const float* as = As + (it & 1) * A_ELE;
        const float* bs = Bs + (it & 1) * B_ELE;
#pragma unroll
        for (int kk = 0; kk < 32; kk += 16) {
            uint32_t af[4][4];
            uint32_t bf[4][2];
#pragma unroll
            for (int mt = 0; mt < 4; mt++) {
                int m = wm * 64 + mt * 16;
                float2 v0 = *(const float2*)&as[(m + gid)     * AS_STRIDE + kk + 2 * tig];
                float2 v1 = *(const float2*)&as[(m + gid + 8) * AS_STRIDE + kk + 2 * tig];
                float2 v2 = *(const float2*)&as[(m + gid)     * AS_STRIDE + kk + 2 * tig + 8];
                float2 v3 = *(const float2*)&as[(m + gid + 8) * AS_STRIDE + kk + 2 * tig + 8];
                af[mt][0] = pack_h2(v0.x, v0.y);
                af[mt][1] = pack_h2(v1.x, v1.y);
                af[mt][2] = pack_h2(v2.x, v2.y);
                af[mt][3] = pack_h2(v3.x, v3.y);
            }
#pragma unroll
            for (int nt = 0; nt < 4; nt++) {
                int n = wn * 32 + nt * 8;
                float b00 = bs[(kk + 2 * tig)     * BS_STRIDE + n + gid];
                float b01 = bs[(kk + 2 * tig + 1) * BS_STRIDE + n + gid];
                float b10 = bs[(kk + 2 * tig + 8) * BS_STRIDE + n + gid];
                float b11 = bs[(kk + 2 * tig + 9) * BS_STRIDE + n + gid];
                bf[nt][0] = pack_h2(b00, b01);
                bf[nt][1] = pack_h2(b10, b11);
            }
#pragma unroll
            for (int mt = 0; mt < 4; mt++)
#pragma unroll
                for (int nt = 0; nt < 4; nt++)
                    mma_f16(acc[mt][nt], af[mt], bf[nt]);
        }
        __syncthreads();
    }

#pragma unroll
    for (int mt = 0; mt < 4; mt++) {
        int row0 = bm + wm * 64 + mt * 16 + gid;
        int row1 = row0 + 8;
#pragma unroll
        for (int nt = 0; nt < 4; nt++) {
            int col = bn + wn * 32 + nt * 8 + tig * 2;
            if (row0 < M)
                *(__half2*)(C + (size_t)row0 * N + col) = __floats2half2_rn(acc[mt][nt].x, acc[mt][nt].y);
            if (row1 < M)
                *(__half2*)(C + (size_t)row1 * N + col) = __floats2half2_rn(acc[mt][nt].z, acc[mt][nt].w);
        }
    }
}

// ---------------- per-node attention scores (fp16 h) ----------------
template <int C>
__global__ void node_scores(const __half* __restrict__ hbuf,
                            const float* __restrict__ asrc,
                            const float* __restrict__ adst,
                            float* __restrict__ es, float* __restrict__ ed) {
    int idx = blockIdx.x * blockDim.x + threadIdx.x;
    if (idx >= NN * NHEADS) return;
    int n = idx >> 3, h = idx & 7;
    const __half2* hp = (const __half2*)(hbuf + (size_t)n * NHEADS * C + h * C);
    const float* ap = asrc + h * C;
    const float* dp = adst + h * C;
    float s = 0.f, d = 0.f;
#pragma unroll
    for (int c = 0; c < C / 2; c++) {
        float2 hv = __half22float2(hp[c]);
        s += hv.x * ap[2 * c] + hv.y * ap[2 * c + 1];
        d += hv.x * dp[2 * c] + hv.y * dp[2 * c + 1];
    }
    es[idx] = s;
    ed[idx] = d;
}

// ---------------- fused CSR aggregation (fp16 gather, fp32 accumulate) ----------------
// 2-edge interleaved loop: all loads for a pair issue before any compute (MLP x2).
// MODE 0: out fp32 = relu(agg + bias)        (layer 1)
// MODE 1: head-mean + bias + log_softmax fused in-warp, write final output (layer 2)
template <int C, int HID, int MODE>
__global__ void gat_aggregate(const int* __restrict__ off, const int* __restrict__ csr,
                              const __half* __restrict__ h,
                              const float* __restrict__ es, const float* __restrict__ ed,
                              const float* __restrict__ bias,
                              float* __restrict__ out) {
    constexpr int CPL = HID / 32;       // channels per lane (8 or 16)
    constexpr int NH = CPL / 8;         // uint4 (8 halves) per lane (1 or 2)
    int lane = threadIdx.x & 31;
    int node = blockIdx.x * 8 + (threadIdx.x >> 5);
    if (node >= NN) return;
    int chbase = lane * CPL;
    int hd = chbase / C;

    float edv = __ldg(ed + (size_t)node * 8 + hd);

    // self loop seed
    float a = __ldg(es + (size_t)node * 8 + hd) + edv;
    a = (a > 0.f) ? a : NEG_SLOPE * a;
    float w = __expf(a);
    float z = w;
    float acc[CPL];
    {
        const uint4* hp = (const uint4*)(h + (size_t)node * HID + chbase);
#pragma unroll
        for (int j = 0; j < NH; j++) {
            uint4 raw = __ldg(hp + j);
            const __half2* hh = (const __half2*)&raw;
#pragma unroll
            for (int q = 0; q < 4; q++) {
                float2 f = __half22float2(hh[q]);
                acc[j * 8 + 2 * q]     = w * f.x;
                acc[j * 8 + 2 * q + 1] = w * f.y;
            }
        }
    }

    int beg = __ldg(off + node), end = __ldg(off + node + 1);
    int i = beg;
    for (; i + 1 < end; i += 2) {
        int sA = __ldg(csr + i);
        int sB = __ldg(csr + i + 1);
        float eA = __ldg(es + (size_t)sA * 8 + hd);
        float eB = __ldg(es + (size_t)sB * 8 + hd);
        const uint4* pA = (const uint4*)(h + (size_t)sA * HID + chbase);
        const uint4* pB = (const uint4*)(h + (size_t)sB * HID + chbase);
        uint4 rA[NH], rB[NH];
#pragma unroll
        for (int j = 0; j < NH; j++) { rA[j] = __ldg(pA + j); rB[j] = __ldg(pB + j); }
        float aA = eA + edv; aA = (aA > 0.f) ? aA : NEG_SLOPE * aA;
        float aB = eB + edv; aB = (aB > 0.f) ? aB : NEG_SLOPE * aB;
        float wA = __expf(aA);
        float wB = __expf(aB);
        z += wA + wB;
#pragma unroll
        for (int j = 0; j < NH; j++) {
            const __half2* hA = (const __half2*)&rA[j];
            const __half2* hB = (const __half2*)&rB[j];
#pragma unroll
            for (int q = 0; q < 4; q++) {
                float2 fA = __half22float2(hA[q]);
                float2 fB = __half22float2(hB[q]);
                acc[j * 8 + 2 * q]     += wA * fA.x + wB * fB.x;
                acc[j * 8 + 2 * q + 1] += wA * fA.y + wB * fB.y;
            }
        }
    }
    if (i < end) {
        int src = __ldg(csr + i);
        float av = __ldg(es + (size_t)src * 8 + hd) + edv;
        av = (av > 0.f) ? av : NEG_SLOPE * av;
        float we = __expf(av);
        z += we;
        const uint4* sp = (const uint4*)(h + (size_t)src * HID + chbase);
#pragma unroll
        for (int j = 0; j < NH; j++) {
            uint4 raw = __ldg(sp + j);
            const __half2* hh = (const __half2*)&raw;
#pragma unroll
            for (int q = 0; q < 4; q++) {
                float2 f = __half22float2(hh[q]);
                acc[j * 8 + 2 * q]     += we * f.x;
                acc[j * 8 + 2 * q + 1] += we * f.y;
            }
        }
    }

    float inv = 1.f / z;

    if (MODE == 0) {
        float4* op = (float4*)(out + (size_t)node * HID + chbase);
#pragma unroll
        for (int j = 0; j < CPL / 4; j++) {
            float4 b = *(const float4*)(bias + chbase + j * 4);
            float4 o;
            o.x = fmaxf(acc[j * 4 + 0] * inv + b.x, 0.f);
            o.y = fmaxf(acc[j * 4 + 1] * inv + b.y, 0.f);
            o.z = fmaxf(acc[j * 4 + 2] * inv + b.z, 0.f);
            o.w = fmaxf(acc[j * 4 + 3] * inv + b.w, 0.f);
            op[j] = o;
        }
    } else {
        // ---- fused: head mean + bias + log_softmax (CPL==16, C==64) ----
        float v[16];
#pragma unroll
        for (int idx = 0; idx < 16; idx++) v[idx] = acc[idx] * inv;
#pragma unroll
        for (int m = 4; m <= 16; m <<= 1)
#pragma unroll
            for (int idx = 0; idx < 16; idx++)
                v[idx] += __shfl_xor_sync(0xffffffffu, v[idx], m);
        int mcls = (lane & 3) * 16;
#pragma unroll
        for (int idx = 0; idx < 16; idx++)
            v[idx] = v[idx] * 0.125f + __ldg(bias + mcls + idx);
        float mx = v[0];
#pragma unroll
        for (int idx = 1; idx < 16; idx++) mx = fmaxf(mx, v[idx]);
        mx = fmaxf(mx, __shfl_xor_sync(0xffffffffu, mx, 1));
        mx = fmaxf(mx, __shfl_xor_sync(0xffffffffu, mx, 2));
        float s = 0.f;
#pragma unroll
        for (int idx = 0; idx < 16; idx++) s += __expf(v[idx] - mx);
        s += __shfl_xor_sync(0xffffffffu, s, 1);
        s += __shfl_xor_sync(0xffffffffu, s, 2);
        float lg = mx + logf(s);
        if (lane < 4) {
            float4* op = (float4*)(out + (size_t)node * NCLS + lane * 16);
#pragma unroll
            for (int j = 0; j < 4; j++)
                op[j] = make_float4(v[j * 4] - lg, v[j * 4 + 1] - lg,
                                    v[j * 4 + 2] - lg, v[j * 4 + 3] - lg);
        }
    }
}

// ---------------- launch ----------------
extern "C" void kernel_launch(void* const* d_in, const int* in_sizes, int n_in,
                              void* d_out, int out_size) {
    const float* x      = (const float*)d_in[0];
    const int*   ei     = (const int*)d_in[1];
    const float* W1     = (const float*)d_in[2];
    const float* a1_src = (const float*)d_in[3];
    const float* a1_dst = (const float*)d_in[4];
    const float* b1     = (const float*)d_in[5];
    const float* W2     = (const float*)d_in[6];
    const float* a2_src = (const float*)d_in[7];
    const float* a2_dst = (const float*)d_in[8];
    const float* b2     = (const float*)d_in[9];
    float* out = (float*)d_out;

    __half *p_h1, *p_h2;
    float *p_agg1, *p_es, *p_ed;
    int *p_deg, *p_off, *p_cur, *p_csr;
    cudaGetSymbolAddress((void**)&p_h1,   g_h1);
    cudaGetSymbolAddress((void**)&p_agg1, g_agg1);
    cudaGetSymbolAddress((void**)&p_h2,   g_h2);
    cudaGetSymbolAddress((void**)&p_es,   g_es);
    cudaGetSymbolAddress((void**)&p_ed,   g_ed);
    cudaGetSymbolAddress((void**)&p_deg,  g_deg);
    cudaGetSymbolAddress((void**)&p_off,  g_off);
    cudaGetSymbolAddress((void**)&p_cur,  g_cur);
    cudaGetSymbolAddress((void**)&p_csr,  g_csr);

    static bool attr_done = false;
    if (!attr_done) {
        cudaFuncSetAttribute(f16gemm, cudaFuncAttributeMaxDynamicSharedMemorySize, GEMM_SMEM);
        attr_done = true;
    }

    // ---------- CSR build (dst-sorted) ----------
    cudaMemsetAsync(p_deg, 0, NN * sizeof(int));
    histogram_kernel<<<(E0 + 255) / 256, 256>>>(ei, p_deg);
    scan_kernel<<<1, 1024>>>(p_deg, p_off, p_cur);
    fill_kernel<<<(E0 + 255) / 256, 256>>>(ei, p_cur, p_csr);

    // ---------- Layer 1 ----------
    {
        dim3 grid(NHID1 / 128, (NN + 127) / 128);
        f16gemm<<<grid, 256, GEMM_SMEM>>>(x, W1, p_h1, NN, NF, NHID1);
    }
    node_scores<C1><<<(NN * NHEADS + 255) / 256, 256>>>(p_h1, a1_src, a1_dst, p_es, p_ed);
    gat_aggregate<C1, NHID1, 0><<<(NN + 7) / 8, 256>>>(p_off, p_csr, p_h1, p_es, p_ed, b1, p_agg1);

    // ---------- Layer 2 ----------
    {
        dim3 grid(NHID2 / 128, (NN + 127) / 128);
        f16gemm<<<grid, 256, GEMM_SMEM>>>(p_agg1, W2, p_h2, NN, NHID1, NHID2);
    }
    node_scores<C2><<<(NN * NHEADS + 255) / 256, 256>>>(p_h2, a2_src, a2_dst, p_es, p_ed);
    gat_aggregate<C2, NHID2, 1><<<(NN + 7) / 8, 256>>>(p_off, p_csr, p_h2, p_es, p_ed, b2, out);
}

// round 16
// speedup vs baseline: 1.0630x; 1.0630x over previous
#include <cuda_runtime.h>
#include <cuda_fp16.h>
#include <cstdint>

#define NN      50000
#define NF      512
#define NHID1   256     // 8 heads * 32
#define NHID2   512     // 8 heads * 64
#define NCLS    64
#define NHEADS  8
#define C1      32
#define C2      64
#define E0      800000
#define NEG_SLOPE 0.2f

// ---------------- scratch (device globals; no allocs allowed) ----------------
__device__ __half g_xh[(size_t)NN * NF];       // x converted to fp16
__device__ __half g_w1h[(size_t)NF * NHID1];
__device__ __half g_w2h[(size_t)NHID1 * NHID2];
__device__ __half g_h1[(size_t)NN * NHID1];
__device__ __half g_agg1[(size_t)NN * NHID1];  // layer1 output, fp16 (GEMM2 A operand)
__device__ __half g_h2[(size_t)NN * NHID2];
__device__ float  g_es[(size_t)NN * NHEADS];
__device__ float  g_ed[(size_t)NN * NHEADS];
__device__ int    g_deg[NN];
__device__ int    g_off[NN + 1];
__device__ int    g_cur[NN];
__device__ int    g_csr[E0];                   // src indices sorted by dst

// ---------------- fp32 -> fp16 convert ----------------
__global__ void f2h_kernel(const float* __restrict__ in, __half* __restrict__ out, int n4) {
    int i = blockIdx.x * blockDim.x + threadIdx.x;
    if (i >= n4) return;
    float4 v = *(const float4*)(in + (size_t)i * 4);
    __half2 h0 = __floats2half2_rn(v.x, v.y);
    __half2 h1 = __floats2half2_rn(v.z, v.w);
    uint2 pk;
    pk.x = *(uint32_t*)&h0;
    pk.y = *(uint32_t*)&h1;
    *(uint2*)(out + (size_t)i * 4) = pk;
}

// ---------------- CSR build ----------------
__global__ void histogram_kernel(const int* __restrict__ ei, int* __restrict__ deg) {
    int e = blockIdx.x * blockDim.x + threadIdx.x;
    if (e >= E0) return;
    atomicAdd(deg + ei[E0 + e], 1);
}

__global__ void scan_kernel(const int* __restrict__ deg, int* __restrict__ off,
                            int* __restrict__ cur) {
    __shared__ int sh[1024];
    int t = threadIdx.x;
    const int CHUNK = (NN + 1023) / 1024;  // 49
    int beg = t * CHUNK;
    int end = min(beg + CHUNK, NN);
    int s = 0;
    for (int i = beg; i < end; i++) s += deg[i];
    sh[t] = s;
    __syncthreads();
    for (int st = 1; st < 1024; st <<= 1) {
        int a = (t >= st) ? sh[t - st] : 0;
        __syncthreads();
        sh[t] += a;
        __syncthreads();
    }
    int run = (t == 0) ? 0 : sh[t - 1];
    for (int i = beg; i < end; i++) {
        off[i] = run;
        cur[i] = run;
        run += deg[i];
    }
    if (t == 1023) off[NN] = E0;
}

__global__ void fill_kernel(const int* __restrict__ ei, int* __restrict__ cur,
                            int* __restrict__ csr) {
    int e = blockIdx.x * blockDim.x + threadIdx.x;
    if (e >= E0) return;
    int src = ei[e];
    int dst = ei[E0 + e];
    int pos = atomicAdd(cur + dst, 1);
    csr[pos] = src;
}

// ---------------- fp16 tensor-core GEMM (ldmatrix + m16n8k16), cp.async 2-stage ----------------
__device__ __forceinline__ void mma_f16(float4& d, const uint32_t* a, const uint32_t* b) {
    asm volatile("mma.sync.aligned.m16n8k16.row.col.f32.f16.f16.f32 "
                 "{%0,%1,%2,%3}, {%4,%5,%6,%7}, {%8,%9}, {%0,%1,%2,%3};"
                 : "+f"(d.x), "+f"(d.y), "+f"(d.z), "+f"(d.w)
                 : "r"(a[0]), "r"(a[1]), "r"(a[2]), "r"(a[3]), "r"(b[0]), "r"(b[1]));
}

__device__ __forceinline__ void ldsm_a4(uint32_t addr, uint32_t* r) {
    asm volatile("ldmatrix.sync.aligned.m8n8.x4.shared.b16 {%0,%1,%2,%3}, [%4];"
                 : "=r"(r[0]), "=r"(r[1]), "=r"(r[2]), "=r"(r[3]) : "r"(addr));
}

__device__ __forceinline__ void ldsm_bt2(uint32_t addr, uint32_t* r) {
    asm volatile("ldmatrix.sync.aligned.m8n8.x2.trans.shared.b16 {%0,%1}, [%2];"
                 : "=r"(r[0]), "=r"(r[1]) : "r"(addr));
}

__device__ __forceinline__ void cp16h(__half* smem, const __half* gmem, bool pred) {
    uint32_t s = (uint32_t)__cvta_generic_to_shared(smem);
    int sz = pred ? 16 : 0;
    asm volatile("cp.async.cg.shared.global [%0], [%1], 16, %2;"
                 :: "r"(s), "l"(gmem), "r"(sz));
}

// C[M,N](fp16) = A[M,K]*B[K,N], all fp16, fp32 accum.
// 128x128x32 tiles, 8 warps, warp tile 64x32, 4x4 m16n8k16 frags.
// As[m=128][k=32] stride 40 halves (80B rows: 16B-aligned, conflict-free ldsm).
// Bs[k=32][n=128] stride 136 halves (272B rows: 16B-aligned, conflict-free ldsm.trans).
#define AS2 40
#define BS2 136
#define A_HALF (128 * AS2)
#define B_HALF (32 * BS2)
#define GEMM_SMEM (2 * (A_HALF + B_HALF) * 2)
__global__ void __launch_bounds__(256, 2)
h16gemm(const __half* __restrict__ A, const __half* __restrict__ B,
        __half* __restrict__ C, int M, int K, int N) {
    extern __shared__ __half smh[];
    __half* As = smh;                  // 2 stages
    __half* Bs = smh + 2 * A_HALF;
    int tid = threadIdx.x;
    int lane = tid & 31;
    int warp = tid >> 5;
    int wm = warp & 1;                 // m-offset 0/64
    int wn = warp >> 1;                // n-offset 0/32/64/96
    int bm = blockIdx.y * 128, bn = blockIdx.x * 128;

    int gid = lane >> 2;
    int tig = lane & 3;

    // fill indices: A 128 rows x 32 halves (64B/row): 4 threads/row, 2 passes
    int arow = tid >> 2;               // 0..63, +64
    int acol = (tid & 3) * 8;          // halves
    // B 32 rows x 128 halves (256B/row): chunks of 8 halves, 512 chunks, 2/thread
    int bchunk = tid;                  // +256

    // ldmatrix lane addressing
    int al = lane & 15;                // A row within 16
    int ah = (lane >> 4) * 8;          // A k-offset (halves)
    int bl = lane & 15;                // B k-row within 16

    uint32_t as_base = (uint32_t)__cvta_generic_to_shared(As);
    uint32_t bs_base = (uint32_t)__cvta_generic_to_shared(Bs);

    float4 acc[4][4];
#pragma unroll
    for (int i = 0; i < 4; i++)
#pragma unroll
        for (int j = 0; j < 4; j++) acc[i][j] = make_float4(0.f, 0.f, 0.f, 0.f);

    int nIter = K >> 5;

    // prologue: stage 0
    {
#pragma unroll
        for (int p = 0; p < 2; p++) {
            int row = arow + p * 64;
            cp16h(&As[row * AS2 + acol], A + (size_t)(bm + row) * K + acol, bm + row < M);
        }
#pragma unroll
        for (int p = 0; p < 2; p++) {
            int ch = bchunk + p * 256;
            int row = ch >> 4;
            int col = (ch & 15) * 8;
            cp16h(&Bs[row * BS2 + col], B + (size_t)row * N + bn + col, true);
        }
        asm volatile("cp.async.commit_group;");
    }

    for (int it = 0; it < nIter; it++) {
        if (it + 1 < nIter) {
            int k0 = (it + 1) << 5;
            __half* as = As + ((it + 1) & 1) * A_HALF;
            __half* bs = Bs + ((it + 1) & 1) * B_HALF;
#pragma unroll
            for (int p = 0; p < 2; p++) {
                int row = arow + p * 64;
                cp16h(&as[row * AS2 + acol], A + (size_t)(bm + row) * K + k0 + acol, bm + row < M);
            }
#pragma unroll
            for (int p = 0; p < 2; p++) {
                int ch = bchunk + p * 256;
                int row = ch >> 4;
                int col = (ch & 15) * 8;
                cp16h(&bs[row * BS2 + col], B + (size_t)(k0 + row) * N + bn + col, true);
            }
            asm volatile("cp.async.commit_group;");
            asm volatile("cp.async.wait_group 1;");
        } else {
            asm volatile("cp.async.wait_group 0;");
        }
        __syncthreads();

        uint32_t asb = as_base + (uint32_t)((it & 1) * A_HALF * 2);
        uint32_t bsb = bs_base + (uint32_t)((it & 1) * B_HALF * 2);
#pragma unroll
        for (int kk = 0; kk < 32; kk += 16) {
            uint32_t af[4][4];
            uint32_t bf[4][2];
#pragma unroll
            for (int mt = 0; mt < 4; mt++) {
                int m0 = wm * 64 + mt * 16;
                uint32_t addr = asb + (uint32_t)((m0 + al) * AS2 + kk + ah) * 2u;
                ldsm_a4(addr, af[mt]);
            }
#pragma unroll
            for (int nt = 0; nt < 4; nt++) {
                int n0 = wn * 32 + nt * 8;
                uint32_t addr = bsb + (uint32_t)((kk + bl) * BS2 + n0) * 2u;
                ldsm_bt2(addr, bf[nt]);
            }
#pragma unroll
            for (int mt = 0; mt < 4; mt++)
#pragma unroll
                for (int nt = 0; nt < 4; nt++)
                    mma_f16(acc[mt][nt], af[mt], bf[nt]);
        }
        __syncthreads();
    }

#pragma unroll
    for (int mt = 0; mt < 4; mt++) {
        int row0 = bm + wm * 64 + mt * 16 + gid;
        int row1 = row0 + 8;
#pragma unroll
        for (int nt = 0; nt < 4; nt++) {
            int col = bn + wn * 32 + nt * 8 + tig * 2;
            if (row0 < M)
                *(__half2*)(C + (size_t)row0 * N + col) = __floats2half2_rn(acc[mt][nt].x, acc[mt][nt].y);
            if (row1 < M)
                *(__half2*)(C + (size_t)row1 * N + col) = __floats2half2_rn(acc[mt][nt].z, acc[mt][nt].w);
        }
    }
}

// ---------------- per-node attention scores (fp16 h) ----------------
template <int C>
__global__ void node_scores(const __half* __restrict__ hbuf,
                            const float* __restrict__ asrc,
                            const float* __restrict__ adst,
                            float* __restrict__ es, float* __restrict__ ed) {
    int idx = blockIdx.x * blockDim.x + threadIdx.x;
    if (idx >= NN * NHEADS) return;
    int n = idx >> 3, h = idx & 7;
    const __half2* hp = (const __half2*)(hbuf + (size_t)n * NHEADS * C + h * C);
    const float* ap = asrc + h * C;
    const float* dp = adst + h * C;
    float s = 0.f, d = 0.f;
#pragma unroll
    for (int c = 0; c < C / 2; c++) {
        float2 hv = __half22float2(hp[c]);
        s += hv.x * ap[2 * c] + hv.y * ap[2 * c + 1];
        d += hv.x * dp[2 * c] + hv.y * dp[2 * c + 1];
    }
    es[idx] = s;
    ed[idx] = d;
}

// ---------------- fused CSR aggregation (fp16 gather, fp32 accumulate) ----------------
// MODE 0: out fp16 = relu(agg + bias)        (layer 1; feeds GEMM2 directly)
// MODE 1: head-mean + bias + log_softmax fused in-warp, write final fp32 output (layer 2)
template <int C, int HID, int MODE>
__global__ void gat_aggregate(const int* __restrict__ off, const int* __restrict__ csr,
                              const __half* __restrict__ h,
                              const float* __restrict__ es, const float* __restrict__ ed,
                              const float* __restrict__ bias,
                              __half* __restrict__ outh, float* __restrict__ outf) {
    constexpr int CPL = HID / 32;       // channels per lane (8 or 16)
    constexpr int NH = CPL / 8;         // uint4 (8 halves) per lane (1 or 2)
    int lane = threadIdx.x & 31;
    int node = blockIdx.x * 8 + (threadIdx.x >> 5);
    if (node >= NN) return;
    int chbase = lane * CPL;
    int hd = chbase / C;

    float edv = __ldg(ed + (size_t)node * 8 + hd);

    // self loop seed
    float a = __ldg(es + (size_t)node * 8 + hd) + edv;
    a = (a > 0.f) ? a : NEG_SLOPE * a;
    float w = __expf(a);
    float z = w;
    float acc[CPL];
    {
        const uint4* hp = (const uint4*)(h + (size_t)node * HID + chbase);
#pragma unroll
        for (int j = 0; j < NH; j++) {
            uint4 raw = __ldg(hp + j);
            const __half2* hh = (const __half2*)&raw;
#pragma unroll
            for (int q = 0; q < 4; q++) {
                float2 f = __half22float2(hh[q]);
                acc[j * 8 + 2 * q]     = w * f.x;
                acc[j * 8 + 2 * q + 1] = w * f.y;
            }
        }
    }

    int beg = __ldg(off + node), end = __ldg(off + node + 1);
    for (int i = beg; i < end; i++) {
        int src = __ldg(csr + i);
        float av = __ldg(es + (size_t)src * 8 + hd) + edv;
        av = (av > 0.f) ? av : NEG_SLOPE * av;
        float we = __expf(av);
        z += we;
        const uint4* sp = (const uint4*)(h + (size_t)src * HID + chbase);
#pragma unroll
        for (int j = 0; j < NH; j++) {
            uint4 raw = __ldg(sp + j);
            const __half2* hh = (const __half2*)&raw;
#pragma unroll
            for (int q = 0; q < 4; q++) {
                float2 f = __half22float2(hh[q]);
                acc[j * 8 + 2 * q]     += we * f.x;
                acc[j * 8 + 2 * q + 1] += we * f.y;
            }
        }
    }

    float inv = 1.f / z;

    if (MODE == 0) {
        // bias + relu -> fp16 (CPL == 8: exactly one uint4 of 8 halves)
        __half2 hp[4];
#pragma unroll
        for (int q = 0; q < 4; q++) {
            float2 b = *(const float2*)(bias + chbase + q * 2);
            float o0 = fmaxf(acc[q * 2 + 0] * inv + b.x, 0.f);
            float o1 = fmaxf(acc[q * 2 + 1] * inv + b.y, 0.f);
            hp[q] = __floats2half2_rn(o0, o1);
        }
        uint4 pk;
        pk.x = *(uint32_t*)&hp[0];
        pk.y = *(uint32_t*)&hp[1];
        pk.z = *(uint32_t*)&hp[2];
        pk.w = *(uint32_t*)&hp[3];
        *(uint4*)(outh + (size_t)node * HID + chbase) = pk;
    } else {
        // ---- fused: head mean + bias + log_softmax (CPL==16, C==64) ----
        float v[16];
#pragma unroll
        for (int idx = 0; idx < 16; idx++) v[idx] = acc[idx] * inv;
#pragma unroll
        for (int m = 4; m <= 16; m <<= 1)
#pragma unroll
            for (int idx = 0; idx < 16; idx++)
                v[idx] += __shfl_xor_sync(0xffffffffu, v[idx], m);
        int mcls = (lane & 3) * 16;
#pragma unroll
        for (int idx = 0; idx < 16; idx++)
            v[idx] = v[idx] * 0.125f + __ldg(bias + mcls + idx);
        float mx = v[0];
#pragma unroll
        for (int idx = 1; idx < 16; idx++) mx = fmaxf(mx, v[idx]);
        mx = fmaxf(mx, __shfl_xor_sync(0xffffffffu, mx, 1));
        mx = fmaxf(mx, __shfl_xor_sync(0xffffffffu, mx, 2));
        float s = 0.f;
#pragma unroll
        for (int idx = 0; idx < 16; idx++) s += __expf(v[idx] - mx);
        s += __shfl_xor_sync(0xffffffffu, s, 1);
        s += __shfl_xor_sync(0xffffffffu, s, 2);
        float lg = mx + logf(s);
        if (lane < 4) {
            float4* op = (float4*)(outf + (size_t)node * NCLS + lane * 16);
#pragma unroll
            for (int j = 0; j < 4; j++)
                op[j] = make_float4(v[j * 4] - lg, v[j * 4 + 1] - lg,
                                    v[j * 4 + 2] - lg, v[j * 4 + 3] - lg);
        }
    }
}

// ---------------- launch ----------------
extern "C" void kernel_launch(void* const* d_in, const int* in_sizes, int n_in,
                              void* d_out, int out_size) {
    const float* x      = (const float*)d_in[0];
    const int*   ei     = (const int*)d_in[1];
    const float* W1     = (const float*)d_in[2];
    const float* a1_src = (const float*)d_in[3];
    const float* a1_dst = (const float*)d_in[4];
    const float* b1     = (const float*)d_in[5];
    const float* W2     = (const float*)d_in[6];
    const float* a2_src = (const float*)d_in[7];
    const float* a2_dst = (const float*)d_in[8];
    const float* b2     = (const float*)d_in[9];
    float* out = (float*)d_out;

    __half *p_xh, *p_w1h, *p_w2h, *p_h1, *p_agg1, *p_h2;
    float *p_es, *p_ed;
    int *p_deg, *p_off, *p_cur, *p_csr;
    cudaGetSymbolAddress((void**)&p_xh,   g_xh);
    cudaGetSymbolAddress((void**)&p_w1h,  g_w1h);
    cudaGetSymbolAddress((void**)&p_w2h,  g_w2h);
    cudaGetSymbolAddress((void**)&p_h1,   g_h1);
    cudaGetSymbolAddress((void**)&p_agg1, g_agg1);
    cudaGetSymbolAddress((void**)&p_h2,   g_h2);
    cudaGetSymbolAddress((void**)&p_es,   g_es);
    cudaGetSymbolAddress((void**)&p_ed,   g_ed);
    cudaGetSymbolAddress((void**)&p_deg,  g_deg);
    cudaGetSymbolAddress((void**)&p_off,  g_off);
    cudaGetSymbolAddress((void**)&p_cur,  g_cur);
    cudaGetSymbolAddress((void**)&p_csr,  g_csr);

    static bool attr_done = false;
    if (!attr_done) {
        cudaFuncSetAttribute(h16gemm, cudaFuncAttributeMaxDynamicSharedMemorySize, GEMM_SMEM);
        attr_done = true;
    }

    // ---------- fp16 conversions ----------
    f2h_kernel<<<(NN * NF / 4 + 255) / 256, 256>>>(x, p_xh, NN * NF / 4);
    f2h_kernel<<<(NF * NHID1 / 4 + 255) / 256, 256>>>(W1, p_w1h, NF * NHID1 / 4);
    f2h_kernel<<<(NHID1 * NHID2 / 4 + 255) / 256, 256>>>(W2, p_w2h, NHID1 * NHID2 / 4);

    // ---------- CSR build (dst-sorted) ----------
    cudaMemsetAsync(p_deg, 0, NN * sizeof(int));
    histogram_kernel<<<(E0 + 255) / 256, 256>>>(ei, p_deg);
    scan_kernel<<<1, 1024>>>(p_deg, p_off, p_cur);
    fill_kernel<<<(E0 + 255) / 256, 256>>>(ei, p_cur, p_csr);

    // ---------- Layer 1 ----------
    {
        dim3 grid(NHID1 / 128, (NN + 127) / 128);
        h16gemm<<<grid, 256, GEMM_SMEM>>>(p_xh, p_w1h, p_h1, NN, NF, NHID1);
    }
    node_scores<C1><<<(NN * NHEADS + 255) / 256, 256>>>(p_h1, a1_src, a1_dst, p_es, p_ed);
    gat_aggregate<C1, NHID1, 0><<<(NN + 7) / 8, 256>>>(p_off, p_csr, p_h1, p_es, p_ed, b1, p_agg1, nullptr);

    // ---------- Layer 2 ----------
    {
        dim3 grid(NHID2 / 128, (NN + 127) / 128);
        h16gemm<<<grid, 256, GEMM_SMEM>>>(p_agg1, p_w2h, p_h2, NN, NHID1, NHID2);
    }
    node_scores<C2><<<(NN * NHEADS + 255) / 256, 256>>>(p_h2, a2_src, a2_dst, p_es, p_ed);
    gat_aggregate<C2, NHID2, 1><<<(NN + 7) / 8, 256>>>(p_off, p_csr, p_h2, p_es, p_ed, b2, nullptr, out);
}